// round 4
// baseline (speedup 1.0000x reference)
#include <cuda_runtime.h>
#include <cuda_fp16.h>
#include <cstdint>

// ============================================================================
// Problem: B=1, S=2048, H=1024, NH=16, D=64, P=2
// out = gated blend of self-attention output and mean-over-P recursive attn.
// fp16 tensor-core (mma.sync m16n8k16, f32 accum) GEMMs + flash attention.
// Round-3: 3-stage cp.async GEMM pipeline (1 barrier/iter), blend fused into
// gate-GEMM epilogue, batched launches for wave packing.
// ============================================================================
#define S_LEN 2048
#define H_DIM 1024

// ---------------------------------------------------------------------------
// Scratch: one static device buffer, manually partitioned. No allocations.
// ---------------------------------------------------------------------------
#define MB_ (1024ull * 1024ull)
__device__ __align__(256) unsigned char g_scratch[112ull * MB_];

#define OFF_H16   (0ull)          // hidden fp16 [2048,1024]            4MB
#define OFF_P16   (4ull*MB_)      // past fp16 [4096,1024]              8MB
#define OFF_WQ    (12ull*MB_)     // each weight fp16 [1024,1024]       2MB
#define OFF_WK    (14ull*MB_)
#define OFF_WV    (16ull*MB_)
#define OFF_WO    (18ull*MB_)
#define OFF_WRQ   (20ull*MB_)
#define OFF_WRK   (22ull*MB_)
#define OFF_WRV   (24ull*MB_)
#define OFF_WG    (26ull*MB_)     // Wg fp16 [2048,1024]                4MB
#define OFF_Q16   (30ull*MB_)     // 4MB each
#define OFF_K16   (34ull*MB_)
#define OFF_V16   (38ull*MB_)
#define OFF_CTX16 (42ull*MB_)
#define OFF_OUTF  (46ull*MB_)     // attention-branch output f32        8MB
#define OFF_OUT16 (54ull*MB_)     // same, fp16                         4MB
#define OFF_RQ16  (58ull*MB_)     // 4MB
#define OFF_RK16  (62ull*MB_)     // [4096,1024] fp16                   8MB
#define OFF_RV16  (70ull*MB_)     // 8MB
#define OFF_RECP  (78ull*MB_)     // per-p recursive ctx f32 2x8MB     16MB
#define OFF_REC   (94ull*MB_)     // mean recursive f32                 8MB
#define OFF_CAT16 (102ull*MB_)    // concat fp16 [2048,2048]            8MB

// ---------------------------------------------------------------------------
// PTX helpers
// ---------------------------------------------------------------------------
__device__ __forceinline__ uint32_t smem_u32(const void* p) {
    return (uint32_t)__cvta_generic_to_shared(p);
}
__device__ __forceinline__ void cp16(uint32_t dst, const void* src) {
    asm volatile("cp.async.cg.shared.global [%0], [%1], 16;\n" :: "r"(dst), "l"(src));
}
__device__ __forceinline__ void cp_commit() {
    asm volatile("cp.async.commit_group;\n" ::: "memory");
}
template<int N> __device__ __forceinline__ void cp_wait() {
    asm volatile("cp.async.wait_group %0;\n" :: "n"(N) : "memory");
}
__device__ __forceinline__ void ldsm4(uint32_t& r0, uint32_t& r1, uint32_t& r2, uint32_t& r3, uint32_t a) {
    asm volatile("ldmatrix.sync.aligned.m8n8.x4.shared.b16 {%0,%1,%2,%3}, [%4];\n"
                 : "=r"(r0), "=r"(r1), "=r"(r2), "=r"(r3) : "r"(a));
}
__device__ __forceinline__ void ldsm4t(uint32_t& r0, uint32_t& r1, uint32_t& r2, uint32_t& r3, uint32_t a) {
    asm volatile("ldmatrix.sync.aligned.m8n8.x4.trans.shared.b16 {%0,%1,%2,%3}, [%4];\n"
                 : "=r"(r0), "=r"(r1), "=r"(r2), "=r"(r3) : "r"(a));
}
__device__ __forceinline__ void mma16816(float (&d)[4], const uint32_t (&a)[4], const uint32_t (&b)[2]) {
    asm volatile(
        "mma.sync.aligned.m16n8k16.row.col.f32.f16.f16.f32 "
        "{%0,%1,%2,%3}, {%4,%5,%6,%7}, {%8,%9}, {%0,%1,%2,%3};\n"
        : "+f"(d[0]), "+f"(d[1]), "+f"(d[2]), "+f"(d[3])
        : "r"(a[0]), "r"(a[1]), "r"(a[2]), "r"(a[3]), "r"(b[0]), "r"(b[1]));
}
__device__ __forceinline__ float ex2f(float x) {
    float y;
    asm("ex2.approx.ftz.f32 %0, %1;" : "=f"(y) : "f"(x));
    return y;
}
__device__ __forceinline__ uint32_t packh2(float a, float b) {
    __half2 h = __floats2half2_rn(a, b);
    return *reinterpret_cast<uint32_t*>(&h);
}

// ============================================================================
// Batched f32 -> f16 convert: blockIdx.y selects the job.
// ============================================================================
#define NCVT 10
struct CvtJobs {
    const float* in[NCVT];
    __half* out[NCVT];
    int n4[NCVT];
};
__global__ void cvt_batch_kernel(CvtJobs j) {
    int job = blockIdx.y;
    int i = blockIdx.x * blockDim.x + threadIdx.x;
    if (i < j.n4[job]) {
        float4 v = reinterpret_cast<const float4*>(j.in[job])[i];
        reinterpret_cast<__half2*>(j.out[job])[2 * i]     = __floats2half2_rn(v.x, v.y);
        reinterpret_cast<__half2*>(j.out[job])[2 * i + 1] = __floats2half2_rn(v.z, v.w);
    }
}

// ============================================================================
// GEMM body: C[M,1024] = A[M,K] @ B[K,1024] + bias.  f16 in, f32 accum.
// 128x128x32 tiles, 256 thr (8 warps 2x4), 3-stage cp.async pipeline.
// Dynamic smem: 3 A-buffers (128x40 halves) + 3 B-buffers (32x136 halves).
// Optional fused blend epilogue: out = bl_a + sigmoid(z)*(bl_b - bl_a).
// ============================================================================
#define SA_BYTES (128 * 40 * 2)      // 10240
#define SB_BYTES (32 * 136 * 2)      // 8704
#define GEMM_SMEM (3 * (SA_BYTES + SB_BYTES))   // 56832

__device__ __forceinline__ void gemm_body(
    const __half* __restrict__ A, const __half* __restrict__ B,
    const float* __restrict__ bias, float* __restrict__ Cf, __half* __restrict__ Ch,
    int K,
    const float* __restrict__ bl_a, const float* __restrict__ bl_b,
    float* __restrict__ bl_out)
{
    const int N = 1024;
    extern __shared__ __align__(16) char dynsmem[];
    __half (*sA)[128][40] = reinterpret_cast<__half(*)[128][40]>(dynsmem);
    __half (*sB)[32][136] = reinterpret_cast<__half(*)[32][136]>(dynsmem + 3 * SA_BYTES);

    const int tid  = threadIdx.x;
    const int lane = tid & 31;
    const int warp = tid >> 5;
    const int wm   = (warp >> 2) << 6;   // 0,64
    const int wn   = (warp & 3) << 5;    // 0,32,64,96
    const int mBase = blockIdx.y * 128;
    const int nBase = blockIdx.x * 128;

    float acc[4][4][4];
#pragma unroll
    for (int a = 0; a < 4; a++)
#pragma unroll
        for (int b = 0; b < 4; b++)
#pragma unroll
            for (int c = 0; c < 4; c++) acc[a][b][c] = 0.f;

    const int Kt = K >> 5;   // always >= 32

    auto load_tiles = [&](int buf, int t) {
#pragma unroll
        for (int i = 0; i < 2; i++) {
            int idx = tid + i * 256;
            int r = idx >> 2, c = (idx & 3) << 3;
            cp16(smem_u32(&sA[buf][r][c]), A + (size_t)(mBase + r) * K + (t << 5) + c);
        }
#pragma unroll
        for (int i = 0; i < 2; i++) {
            int idx = tid + i * 256;
            int r = idx >> 4, c = (idx & 15) << 3;
            cp16(smem_u32(&sB[buf][r][c]), B + (size_t)((t << 5) + r) * N + nBase + c);
        }
        cp_commit();
    };

    load_tiles(0, 0);
    load_tiles(1, 1);
    int cur = 0;     // buffer holding tile t
    int ldb = 2;     // buffer to load tile t+2 into

    for (int t = 0; t < Kt; t++) {
        // pending groups entering iter t: {t, t+1}; wait<1> drains group t.
        if (t + 1 < Kt) cp_wait<1>(); else cp_wait<0>();
        __syncthreads();   // also orders iter t-1's reads of buffer 'ldb' before writes below
#pragma unroll
        for (int ks = 0; ks < 2; ks++) {
            uint32_t af[4][4];
#pragma unroll
            for (int mi = 0; mi < 4; mi++)
                ldsm4(af[mi][0], af[mi][1], af[mi][2], af[mi][3],
                      smem_u32(&sA[cur][wm + mi * 16 + (lane & 15)][ks * 16 + ((lane >> 4) << 3)]));
            uint32_t bf[4][2];
#pragma unroll
            for (int j = 0; j < 2; j++) {
                uint32_t r0, r1, r2, r3;
                ldsm4t(r0, r1, r2, r3,
                       smem_u32(&sB[cur][ks * 16 + (((lane >> 3) & 1) << 3) + (lane & 7)]
                                        [wn + j * 16 + ((lane >> 4) << 3)]));
                bf[2 * j][0] = r0; bf[2 * j][1] = r1;
                bf[2 * j + 1][0] = r2; bf[2 * j + 1][1] = r3;
            }
#pragma unroll
            for (int mi = 0; mi < 4; mi++)
#pragma unroll
                for (int ni = 0; ni < 4; ni++)
                    mma16816(acc[mi][ni], af[mi], bf[ni]);
        }
        if (t + 2 < Kt) load_tiles(ldb, t + 2);
        cur = (cur == 2) ? 0 : cur + 1;
        ldb = (ldb == 2) ? 0 : ldb + 1;
    }

    // epilogue
#pragma unroll
    for (int ni = 0; ni < 4; ni++) {
        int col = nBase + wn + ni * 8 + ((lane & 3) << 1);
        float b0 = bias[col], b1 = bias[col + 1];
#pragma unroll
        for (int mi = 0; mi < 4; mi++) {
            int row0 = mBase + wm + mi * 16 + (lane >> 2);
            int row1 = row0 + 8;
            float c0 = acc[mi][ni][0] + b0, c1 = acc[mi][ni][1] + b1;
            float c2 = acc[mi][ni][2] + b0, c3 = acc[mi][ni][3] + b1;
            if (bl_out) {
                // fused gate: out = a + sigmoid(z)*(b - a)
                size_t i0 = (size_t)row0 * N + col, i1 = (size_t)row1 * N + col;
                float g0 = 1.f / (1.f + __expf(-c0));
                float g1 = 1.f / (1.f + __expf(-c1));
                float g2 = 1.f / (1.f + __expf(-c2));
                float g3 = 1.f / (1.f + __expf(-c3));
                float2 a0v = *reinterpret_cast<const float2*>(bl_a + i0);
                float2 b0v = *reinterpret_cast<const float2*>(bl_b + i0);
                float2 a1v = *reinterpret_cast<const float2*>(bl_a + i1);
                float2 b1v = *reinterpret_cast<const float2*>(bl_b + i1);
                *reinterpret_cast<float2*>(bl_out + i0) =
                    make_float2(a0v.x + g0 * (b0v.x - a0v.x), a0v.y + g1 * (b0v.y - a0v.y));
                *reinterpret_cast<float2*>(bl_out + i1) =
                    make_float2(a1v.x + g2 * (b1v.x - a1v.x), a1v.y + g3 * (b1v.y - a1v.y));
            }
            if (Cf) {
                *reinterpret_cast<float2*>(Cf + (size_t)row0 * N + col) = make_float2(c0, c1);
                *reinterpret_cast<float2*>(Cf + (size_t)row1 * N + col) = make_float2(c2, c3);
            }
            if (Ch) {
                *reinterpret_cast<__half2*>(Ch + (size_t)row0 * N + col) = __floats2half2_rn(c0, c1);
                *reinterpret_cast<__half2*>(Ch + (size_t)row1 * N + col) = __floats2half2_rn(c2, c3);
            }
        }
    }
}

// single-job GEMM entry
__global__ void __launch_bounds__(256) gemm_f16_kernel(
    const __half* __restrict__ A, const __half* __restrict__ B,
    const float* __restrict__ bias, float* __restrict__ Cf, __half* __restrict__ Ch, int K,
    const float* __restrict__ bl_a, const float* __restrict__ bl_b, float* __restrict__ bl_out)
{
    gemm_body(A, B, bias, Cf, Ch, K, bl_a, bl_b, bl_out);
}

// batched GEMM entry: blockIdx.z selects {B, bias, Ch}; shared A, K=1024, f16-out.
struct GemmBatch {
    const __half* A;
    const __half* B[3];
    const float* bias[3];
    __half* Ch[3];
};
__global__ void __launch_bounds__(256) gemm_f16_batch_kernel(GemmBatch g) {
    int z = blockIdx.z;
    gemm_body(g.A, g.B[z], g.bias[z], nullptr, g.Ch[z], 1024, nullptr, nullptr, nullptr);
}

// ============================================================================
// Flash attention body: one CTA = (head, 128-query block). 64-key blocks.
// Q,K,V fp16 [2048,1024] layouts (head h = cols h*64..h*64+63).
// Online softmax in exp2 domain. Output f16 and/or f32.
// ============================================================================
__device__ __forceinline__ void attn_body(
    const __half* __restrict__ Qg, const __half* __restrict__ Kg,
    const __half* __restrict__ Vg, __half* __restrict__ o16, float* __restrict__ o32)
{
    const int qblk = blockIdx.x;   // 16
    const int head = blockIdx.y;   // 16
    const int tid  = threadIdx.x;
    const int lane = tid & 31;
    const int warp = tid >> 5;

    __shared__ __align__(16) __half sm[2][2][64][72];   // [buf][K/V][row][d]

    const __half* Qh = Qg + (size_t)qblk * 128 * H_DIM + head * 64;
    const __half* Kh = Kg + head * 64;
    const __half* Vh = Vg + head * 64;

    // ---- stage Q (128x64) through smem, ldmatrix into regs ----
    {
        __half* qs = &sm[0][0][0][0];   // 128 rows x stride 72
#pragma unroll
        for (int i = 0; i < 4; i++) {
            int idx = tid + i * 256;
            int r = idx >> 3, c = (idx & 7) << 3;
            cp16(smem_u32(qs + r * 72 + c), Qh + (size_t)r * H_DIM + c);
        }
        cp_commit(); cp_wait<0>();
        __syncthreads();
    }
    uint32_t qf[4][4];
    {
        __half* qs = &sm[0][0][0][0];
#pragma unroll
        for (int kt = 0; kt < 4; kt++)
            ldsm4(qf[kt][0], qf[kt][1], qf[kt][2], qf[kt][3],
                  smem_u32(qs + (warp * 16 + (lane & 15)) * 72 + kt * 16 + ((lane >> 4) << 3)));
    }
    __syncthreads();

    auto loadKV = [&](int buf, int blk) {
#pragma unroll
        for (int i = 0; i < 2; i++) {
            int idx = tid + i * 256;
            int r = idx >> 3, c = (idx & 7) << 3;
            cp16(smem_u32(&sm[buf][0][r][c]), Kh + (size_t)(blk * 64 + r) * H_DIM + c);
        }
#pragma unroll
        for (int i = 0; i < 2; i++) {
            int idx = tid + i * 256;
            int r = idx >> 3, c = (idx & 7) << 3;
            cp16(smem_u32(&sm[buf][1][r][c]), Vh + (size_t)(blk * 64 + r) * H_DIM + c);
        }
        cp_commit();
    };

    loadKV(0, 0);
    loadKV(1, 1);
    int cur = 0;

    const float C = 0.125f * 1.4426950408889634f;  // SCALE * log2(e)
    float m2[2] = {-1e30f, -1e30f};
    float l[2]  = {0.f, 0.f};
    float o[8][4];
#pragma unroll
    for (int ni = 0; ni < 8; ni++)
#pragma unroll
        for (int c = 0; c < 4; c++) o[ni][c] = 0.f;

    const int NB = S_LEN / 64;   // 32
    for (int b = 0; b < NB; b++) {
        if (b == NB - 1) cp_wait<0>(); else cp_wait<1>();
        __syncthreads();

        // ---- S = Q K^T  (per-warp m16 x n64, k=64) ----
        float s[8][4];
#pragma unroll
        for (int ni = 0; ni < 8; ni++)
#pragma unroll
            for (int c = 0; c < 4; c++) s[ni][c] = 0.f;

#pragma unroll
        for (int kt = 0; kt < 4; kt++) {
            uint32_t bk[8][2];
#pragma unroll
            for (int j = 0; j < 4; j++) {   // 16 keys per ldsm4
                uint32_t r0, r1, r2, r3;
                ldsm4(r0, r1, r2, r3,
                      smem_u32(&sm[cur][0][j * 16 + (((lane >> 3) & 1) << 3) + (lane & 7)]
                                          [kt * 16 + ((lane >> 4) << 3)]));
                bk[2 * j][0] = r0; bk[2 * j][1] = r2;
                bk[2 * j + 1][0] = r1; bk[2 * j + 1][1] = r3;
            }
#pragma unroll
            for (int ni = 0; ni < 8; ni++)
                mma16816(s[ni], qf[kt], bk[ni]);
        }

        // ---- online softmax (rows r = lane>>2 and r+8) ----
#pragma unroll
        for (int ni = 0; ni < 8; ni++)
#pragma unroll
            for (int c = 0; c < 4; c++) s[ni][c] *= C;

        float mx0 = -1e30f, mx1 = -1e30f;
#pragma unroll
        for (int ni = 0; ni < 8; ni++) {
            mx0 = fmaxf(mx0, fmaxf(s[ni][0], s[ni][1]));
            mx1 = fmaxf(mx1, fmaxf(s[ni][2], s[ni][3]));
        }
        mx0 = fmaxf(mx0, __shfl_xor_sync(0xffffffffu, mx0, 1));
        mx0 = fmaxf(mx0, __shfl_xor_sync(0xffffffffu, mx0, 2));
        mx1 = fmaxf(mx1, __shfl_xor_sync(0xffffffffu, mx1, 1));
        mx1 = fmaxf(mx1, __shfl_xor_sync(0xffffffffu, mx1, 2));

        float mn0 = fmaxf(m2[0], mx0), mn1 = fmaxf(m2[1], mx1);
        float a0 = ex2f(m2[0] - mn0), a1 = ex2f(m2[1] - mn1);
        m2[0] = mn0; m2[1] = mn1;

        uint32_t pp[8][2];
        float sum0 = 0.f, sum1 = 0.f;
#pragma unroll
        for (int ni = 0; ni < 8; ni++) {
            float p00 = ex2f(s[ni][0] - mn0), p01 = ex2f(s[ni][1] - mn0);
            float p10 = ex2f(s[ni][2] - mn1), p11 = ex2f(s[ni][3] - mn1);
            sum0 += p00 + p01; sum1 += p10 + p11;
            pp[ni][0] = packh2(p00, p01);
            pp[ni][1] = packh2(p10, p11);
        }
        sum0 += __shfl_xor_sync(0xffffffffu, sum0, 1);
        sum0 += __shfl_xor_sync(0xffffffffu, sum0, 2);
        sum1 += __shfl_xor_sync(0xffffffffu, sum1, 1);
        sum1 += __shfl_xor_sync(0xffffffffu, sum1, 2);
        l[0] = l[0] * a0 + sum0;
        l[1] = l[1] * a1 + sum1;

#pragma unroll
        for (int ni = 0; ni < 8; ni++) {
            o[ni][0] *= a0; o[ni][1] *= a0;
            o[ni][2] *= a1; o[ni][3] *= a1;
        }

        // ---- O += P @ V  (k = 64 keys) ----
#pragma unroll
        for (int kt = 0; kt < 4; kt++) {
            uint32_t pf[4] = { pp[2 * kt][0], pp[2 * kt][1], pp[2 * kt + 1][0], pp[2 * kt + 1][1] };
            uint32_t vf[8][2];
#pragma unroll
            for (int j = 0; j < 4; j++) {   // d-tiles 2j, 2j+1
                uint32_t r0, r1, r2, r3;
                ldsm4t(r0, r1, r2, r3,
                       smem_u32(&sm[cur][1][kt * 16 + (((lane >> 3) & 1) << 3) + (lane & 7)]
                                           [j * 16 + ((lane >> 4) << 3)]));
                vf[2 * j][0] = r0; vf[2 * j][1] = r1;
                vf[2 * j + 1][0] = r2; vf[2 * j + 1][1] = r3;
            }
#pragma unroll
            for (int ni = 0; ni < 8; ni++)
                mma16816(o[ni], pf, vf[ni]);
        }

        __syncthreads();
        if (b + 2 < NB) loadKV(cur, b + 2);
        cur ^= 1;
    }

    // ---- normalize + write ----
    float inv0 = 1.f / l[0], inv1 = 1.f / l[1];
    int row0 = qblk * 128 + warp * 16 + (lane >> 2);
    int row1 = row0 + 8;
#pragma unroll
    for (int ni = 0; ni < 8; ni++) {
        int col = head * 64 + ni * 8 + ((lane & 3) << 1);
        float c0 = o[ni][0] * inv0, c1 = o[ni][1] * inv0;
        float c2 = o[ni][2] * inv1, c3 = o[ni][3] * inv1;
        if (o16) {
            *reinterpret_cast<__half2*>(o16 + (size_t)row0 * H_DIM + col) = __floats2half2_rn(c0, c1);
            *reinterpret_cast<__half2*>(o16 + (size_t)row1 * H_DIM + col) = __floats2half2_rn(c2, c3);
        }
        if (o32) {
            *reinterpret_cast<float2*>(o32 + (size_t)row0 * H_DIM + col) = make_float2(c0, c1);
            *reinterpret_cast<float2*>(o32 + (size_t)row1 * H_DIM + col) = make_float2(c2, c3);
        }
    }
}

// self-attention entry (f16 output)
__global__ void __launch_bounds__(256) attn_kernel(
    const __half* __restrict__ Qg, const __half* __restrict__ Kg,
    const __half* __restrict__ Vg, __half* __restrict__ o16)
{
    attn_body(Qg, Kg, Vg, o16, nullptr);
}

// batched recursive attention: blockIdx.z = p selects KV slice + f32 output.
__global__ void __launch_bounds__(256) attn_rec_kernel(
    const __half* __restrict__ Qg, const __half* __restrict__ Kg,
    const __half* __restrict__ Vg, float* __restrict__ o32a, float* __restrict__ o32b)
{
    int p = blockIdx.z;
    const size_t sl = (size_t)2048 * 1024;
    attn_body(Qg, Kg + p * sl, Vg + p * sl, nullptr, p == 0 ? o32a : o32b);
}

// ============================================================================
// mean over P + build concat buffer [out16 | f16(rec)]
// ============================================================================
__global__ void meanpack_kernel(
    const float* __restrict__ r0, const float* __restrict__ r1,
    const __half* __restrict__ out16, float* __restrict__ rec, __half* __restrict__ cat)
{
    int i = blockIdx.x * blockDim.x + threadIdx.x;
    if (i < S_LEN * H_DIM) {
        int row = i >> 10, col = i & 1023;
        float m = 0.5f * (r0[i] + r1[i]);
        rec[i] = m;
        cat[(size_t)row * 2048 + col] = out16[i];
        cat[(size_t)row * 2048 + 1024 + col] = __float2half(m);
    }
}

// ============================================================================
// launch
// ============================================================================
extern "C" void kernel_launch(void* const* d_in, const int* in_sizes, int n_in,
                              void* d_out, int out_size)
{
    unsigned char* base = nullptr;
    cudaGetSymbolAddress((void**)&base, g_scratch);

    // opt-in to >48KB dynamic smem for the GEMM kernels (host-side, idempotent)
    cudaFuncSetAttribute(gemm_f16_kernel, cudaFuncAttributeMaxDynamicSharedMemorySize, GEMM_SMEM);
    cudaFuncSetAttribute(gemm_f16_batch_kernel, cudaFuncAttributeMaxDynamicSharedMemorySize, GEMM_SMEM);

    const float* hidden = (const float*)d_in[0];
    const float* past   = (const float*)d_in[1];
    const float* Wq = (const float*)d_in[2];  const float* bq = (const float*)d_in[3];
    const float* Wk = (const float*)d_in[4];  const float* bk = (const float*)d_in[5];
    const float* Wv = (const float*)d_in[6];  const float* bv = (const float*)d_in[7];
    const float* Wo = (const float*)d_in[8];  const float* bo = (const float*)d_in[9];
    const float* Wrq = (const float*)d_in[10]; const float* brq = (const float*)d_in[11];
    const float* Wrk = (const float*)d_in[12]; const float* brk = (const float*)d_in[13];
    const float* Wrv = (const float*)d_in[14]; const float* brv = (const float*)d_in[15];
    const float* Wg = (const float*)d_in[16];  const float* bg = (const float*)d_in[17];

    __half* h16   = (__half*)(base + OFF_H16);
    __half* p16   = (__half*)(base + OFF_P16);
    __half* wq16  = (__half*)(base + OFF_WQ);
    __half* wk16  = (__half*)(base + OFF_WK);
    __half* wv16  = (__half*)(base + OFF_WV);
    __half* wo16  = (__half*)(base + OFF_WO);
    __half* wrq16 = (__half*)(base + OFF_WRQ);
    __half* wrk16 = (__half*)(base + OFF_WRK);
    __half* wrv16 = (__half*)(base + OFF_WRV);
    __half* wg16  = (__half*)(base + OFF_WG);
    __half* q16   = (__half*)(base + OFF_Q16);
    __half* k16   = (__half*)(base + OFF_K16);
    __half* v16   = (__half*)(base + OFF_V16);
    __half* ctx16 = (__half*)(base + OFF_CTX16);
    float*  outf  = (float*)(base + OFF_OUTF);
    __half* out16 = (__half*)(base + OFF_OUT16);
    __half* rq16  = (__half*)(base + OFF_RQ16);
    __half* rk16  = (__half*)(base + OFF_RK16);
    __half* rv16  = (__half*)(base + OFF_RV16);
    float*  recp0 = (float*)(base + OFF_RECP);
    float*  recp1 = (float*)(base + OFF_RECP + 8ull * MB_);
    float*  rec   = (float*)(base + OFF_REC);
    __half* cat16 = (__half*)(base + OFF_CAT16);

    const int n1M = 1024 * 1024, n2M = 2048 * 1024, n4M = 4096 * 1024;

    // ---- all converts in one batched launch ----
    {
        CvtJobs j;
        const float* ins[NCVT]  = { hidden, past, Wq, Wk, Wv, Wo, Wrq, Wrk, Wrv, Wg };
        __half* outs[NCVT]      = { h16, p16, wq16, wk16, wv16, wo16, wrq16, wrk16, wrv16, wg16 };
        int ns[NCVT]            = { n2M, n4M, n1M, n1M, n1M, n1M, n1M, n1M, n1M, n2M };
        int maxn4 = 0;
        for (int i = 0; i < NCVT; i++) {
            j.in[i] = ins[i]; j.out[i] = outs[i]; j.n4[i] = ns[i] >> 2;
            if (j.n4[i] > maxn4) maxn4 = j.n4[i];
        }
        dim3 g((maxn4 + 255) / 256, NCVT);
        cvt_batch_kernel<<<g, 256>>>(j);
    }

    dim3 gemmGrid2k(8, 16);     // M=2048
    dim3 attnGrid(16, 16);      // (qblk, head)

    // ---- Q/K/V projections: one batched launch (384 CTAs) ----
    {
        GemmBatch g;
        g.A = h16;
        g.B[0] = wq16; g.B[1] = wk16; g.B[2] = wv16;
        g.bias[0] = bq; g.bias[1] = bk; g.bias[2] = bv;
        g.Ch[0] = q16; g.Ch[1] = k16; g.Ch[2] = v16;
        gemm_f16_batch_kernel<<<dim3(8, 16, 3), 256, GEMM_SMEM>>>(g);
    }

    // self attention + O projection (f32 + f16 outputs)
    attn_kernel<<<attnGrid, 256>>>(q16, k16, v16, ctx16);
    gemm_f16_kernel<<<gemmGrid2k, 256, GEMM_SMEM>>>(ctx16, wo16, bo, outf, out16, 1024,
                                                    nullptr, nullptr, nullptr);

    // ---- recursive branch ----
    gemm_f16_kernel<<<gemmGrid2k, 256, GEMM_SMEM>>>(out16, wrq16, brq, nullptr, rq16, 1024,
                                                    nullptr, nullptr, nullptr);
    {
        GemmBatch g;
        g.A = p16;
        g.B[0] = wrk16; g.B[1] = wrv16; g.B[2] = wrv16;   // [2] unused
        g.bias[0] = brk; g.bias[1] = brv; g.bias[2] = brv;
        g.Ch[0] = rk16; g.Ch[1] = rv16; g.Ch[2] = rv16;
        gemm_f16_batch_kernel<<<dim3(8, 32, 2), 256, GEMM_SMEM>>>(g);
    }
    // two recursive attention passes in one launch (512 CTAs)
    attn_rec_kernel<<<dim3(16, 16, 2), 256>>>(rq16, rk16, rv16, recp0, recp1);

    // ---- mean + concat, then gate GEMM with fused sigmoid-blend epilogue ----
    meanpack_kernel<<<(n2M + 255) / 256, 256>>>(recp0, recp1, out16, rec, cat16);
    gemm_f16_kernel<<<gemmGrid2k, 256, GEMM_SMEM>>>(cat16, wg16, bg, nullptr, nullptr, 2048,
                                                    outf, rec, (float*)d_out);
}